// round 2
// baseline (speedup 1.0000x reference)
#include <cuda_runtime.h>
#include <cstddef>

// Problem constants (B=64, T=8192, C=64), verified via in_sizes at launch.
#define FFT_N    8192
#define LOG_N    13
#define NT       512
#define CH       64
#define TWO_PI_F 6.283185307179586476925f

__device__ __forceinline__ float2 cmul(float2 a, float2 b) {
    return make_float2(fmaf(a.x, b.x, -a.y * b.y), fmaf(a.x, b.y, a.y * b.x));
}

// One CTA handles channels (c0, c0+1) of one batch b.
// Packs the two real series into one complex series:
//   forward FFT once, Hermitian unpack for per-channel amplitudes,
//   random phases -> Hermitian-symmetrized spectra H1, H2,
//   single inverse FFT of H1 + i*H2 gives both surrogate series (Re, Im).
__global__ __launch_bounds__(NT, 1)
void surrogate_kernel(const float* __restrict__ wave,
                      const float* __restrict__ phases,
                      const float* __restrict__ mask,
                      float* __restrict__ out) {
    const int blk = blockIdx.x;
    const int b   = blk >> 5;          // C/2 = 32 channel-pairs per batch
    const int c0  = (blk & 31) * 2;
    const int tid = threadIdx.x;

    const bool s0 = mask[b * CH + c0]     < 0.5f;   // use surrogate for ch c0?
    const bool s1 = mask[b * CH + c0 + 1] < 0.5f;

    const float* wbase = wave   + (size_t)b * FFT_N * CH + c0;
    const float* pbase = phases + (size_t)b * FFT_N * CH + c0;
    float*       obase = out    + (size_t)b * FFT_N * CH + c0;

    if (!s0 && !s1) {
        // Both channels keep the original: pure copy, skip all FFT work.
        #pragma unroll 4
        for (int t = tid; t < FFT_N; t += NT) {
            *(float2*)(obase + (size_t)t * CH) = *(const float2*)(wbase + (size_t)t * CH);
        }
        return;
    }

    extern __shared__ float2 sm[];
    float2* bufA = sm;                 // 8192 complex
    float2* bufB = sm + FFT_N;         // 8192 complex
    float2* tw   = sm + 2 * FFT_N;     // 4096 twiddles: tw[j] = e^{-2*pi*i*j/N}

    // Build twiddle LUT (one-time, accurate).
    for (int j = tid; j < FFT_N / 2; j += NT) {
        float sj, cj;
        sincospif(-2.0f * (float)j / (float)FFT_N, &sj, &cj);
        tw[j] = make_float2(cj, sj);
    }

    // Load both channels packed as complex; channels that keep the original
    // are written to out right now (their data is about to be destroyed).
    #pragma unroll 4
    for (int t = tid; t < FFT_N; t += NT) {
        float2 v = *(const float2*)(wbase + (size_t)t * CH);
        bufA[t] = v;
        if (!s0) obase[(size_t)t * CH]     = v.x;
        if (!s1) obase[(size_t)t * CH + 1] = v.y;
    }
    __syncthreads();

    // ---------------- Forward FFT (Stockham DIF, radix-2, autosort) -------
    float2* src = bufA;
    float2* dst = bufB;
    #pragma unroll 1
    for (int ls = 0; ls < LOG_N; ls++) {
        const int s     = 1 << ls;
        const int sMask = s - 1;
        #pragma unroll
        for (int i = 0; i < FFT_N / 2 / NT; i++) {
            const int idx = tid + i * NT;
            const int hi  = idx & ~sMask;          // s * p
            float2 a = src[idx];
            float2 c = src[idx + FFT_N / 2];
            float2 w = tw[hi];
            float2 dif = make_float2(a.x - c.x, a.y - c.y);
            dst[idx + hi]     = make_float2(a.x + c.x, a.y + c.y);
            dst[idx + hi + s] = cmul(dif, w);
        }
        __syncthreads();
        float2* t2 = src; src = dst; dst = t2;
    }
    // Forward result Z now in src (== bufB after 13 swaps).

    // ---------------- Spectrum rebuild ------------------------------------
    // Z = FFT(x1 + i*x2).  X1_k = (Z_k + conj(Z_{N-k}))/2 ; X2_k = -i(Z_k - conj(Z_{N-k}))/2.
    // Amplitudes are exactly symmetric (A_{N-k} = A_k) under this split.
    // Y_i(k) = A_i(k) e^{i phi_i(k)};  H_i(k) = (Y_i(k) + conj(Y_i(N-k)))/2 is Hermitian.
    // W = H1 + i*H2;  IFFT(W) = surr1 + i*surr2 (both real).
    {
        const float2* Z = src;
        float2*       W = dst;
        const float scale = 0.25f / (float)FFT_N;  // 0.5 (unpack) * 0.5 (symm) * 1/N (ifft)
        for (int k = tid; k <= FFT_N / 2; k += NT) {
            const int nk = (FFT_N - k) & (FFT_N - 1);
            float2 z1 = Z[k];
            float2 z2 = Z[nk];
            // |X1| and |X2| (scaled)
            float ax = z1.x + z2.x, ay = z1.y - z2.y;
            float bx = z1.y + z2.y, by = z2.x - z1.x;
            float amp1 = sqrtf(fmaf(ax, ax, ay * ay)) * scale;
            float amp2 = sqrtf(fmaf(bx, bx, by * by)) * scale;

            float2 pk  = *(const float2*)(pbase + (size_t)k  * CH);
            float2 pnk = *(const float2*)(pbase + (size_t)nk * CH);
            float s1k, c1k, s1n, c1n, s2k, c2k, s2n, c2n;
            __sincosf(TWO_PI_F * pk.x,  &s1k, &c1k);
            __sincosf(TWO_PI_F * pnk.x, &s1n, &c1n);
            __sincosf(TWO_PI_F * pk.y,  &s2k, &c2k);
            __sincosf(TWO_PI_F * pnk.y, &s2n, &c2n);

            float h1x = amp1 * (c1k + c1n), h1y = amp1 * (s1k - s1n);
            float h2x = amp2 * (c2k + c2n), h2y = amp2 * (s2k - s2n);

            W[k]  = make_float2(h1x - h2y, h1y + h2x);
            W[nk] = make_float2(h1x + h2y, h2x - h1y);   // conj(H1) + i*conj(H2)
        }
    }
    __syncthreads();

    // ---------------- Inverse FFT (conjugate twiddles, scale pre-folded) --
    src = bufA;   // W was written into bufA (dst after fwd)
    dst = bufB;
    #pragma unroll 1
    for (int ls = 0; ls < LOG_N; ls++) {
        const int s     = 1 << ls;
        const int sMask = s - 1;
        #pragma unroll
        for (int i = 0; i < FFT_N / 2 / NT; i++) {
            const int idx = tid + i * NT;
            const int hi  = idx & ~sMask;
            float2 a = src[idx];
            float2 c = src[idx + FFT_N / 2];
            float2 w = tw[hi];
            w.y = -w.y;                              // conjugate twiddle
            float2 dif = make_float2(a.x - c.x, a.y - c.y);
            dst[idx + hi]     = make_float2(a.x + c.x, a.y + c.y);
            dst[idx + hi + s] = cmul(dif, w);
        }
        __syncthreads();
        float2* t2 = src; src = dst; dst = t2;
    }
    // Result in src (== bufB). Re = surrogate(c0), Im = surrogate(c0+1).

    if (s0 && s1) {
        #pragma unroll 4
        for (int t = tid; t < FFT_N; t += NT) {
            *(float2*)(obase + (size_t)t * CH) = src[t];
        }
    } else if (s0) {
        #pragma unroll 4
        for (int t = tid; t < FFT_N; t += NT) {
            obase[(size_t)t * CH] = src[t].x;
        }
    } else {
        #pragma unroll 4
        for (int t = tid; t < FFT_N; t += NT) {
            obase[(size_t)t * CH + 1] = src[t].y;
        }
    }
}

extern "C" void kernel_launch(void* const* d_in, const int* in_sizes, int n_in,
                              void* d_out, int out_size) {
    const float* wave   = (const float*)d_in[0];
    const float* phases = (const float*)d_in[1];
    const float* maskp  = (const float*)d_in[2];
    float* out = (float*)d_out;

    const int B = in_sizes[0] / (FFT_N * CH);     // 64
    const int smem = (2 * FFT_N + FFT_N / 2) * (int)sizeof(float2);  // 160 KB

    cudaFuncSetAttribute(surrogate_kernel,
                         cudaFuncAttributeMaxDynamicSharedMemorySize, smem);
    surrogate_kernel<<<B * (CH / 2), NT, smem>>>(wave, phases, maskp, out);
}

// round 3
// speedup vs baseline: 1.3243x; 1.3243x over previous
#include <cuda_runtime.h>
#include <cstddef>

#define FFT_N 8192
#define NT    512
#define CH    64

// Padded layout for bufB: 1 extra float2 per 16 -> conflict-free scatter at s=1.
#define PADI(a) ((a) + ((a) >> 4))

__device__ __forceinline__ float2 cmul(float2 a, float2 b) {
    return make_float2(fmaf(a.x, b.x, -a.y * b.y), fmaf(a.x, b.y, a.y * b.x));
}
__device__ __forceinline__ float2 cadd(float2 a, float2 b) { return make_float2(a.x + b.x, a.y + b.y); }
__device__ __forceinline__ float2 csub(float2 a, float2 b) { return make_float2(a.x - b.x, a.y - b.y); }

// In-place DFT4. DIR=+1: forward (w = e^{-2pi i/4} = -i), DIR=-1: inverse.
template<int DIR>
__device__ __forceinline__ void dft4(float2& a, float2& b, float2& c, float2& d) {
    float2 t0 = cadd(a, c), t1 = csub(a, c);
    float2 t2 = cadd(b, d), t3 = csub(b, d);
    a = cadd(t0, t2);
    c = csub(t0, t2);
    if (DIR > 0) {
        b = make_float2(t1.x + t3.y, t1.y - t3.x);   // t1 - i*t3
        d = make_float2(t1.x - t3.y, t1.y + t3.x);   // t1 + i*t3
    } else {
        b = make_float2(t1.x - t3.y, t1.y + t3.x);
        d = make_float2(t1.x + t3.y, t1.y - t3.x);
    }
}

// In-place DFT16 (two levels of radix-4). After the call, output X[k2+4*k1]
// lives in slot 4*k2+k1; callers permute on store: slot(o) = ((o&3)<<2)|(o>>2).
template<int DIR>
__device__ __forceinline__ void dft16(float2 v[16]) {
    #pragma unroll
    for (int n1 = 0; n1 < 4; n1++)
        dft4<DIR>(v[n1], v[n1 + 4], v[n1 + 8], v[n1 + 12]);
    const float C1 = 0.92387953251128674f;   // cos(2pi/16)
    const float S1 = 0.38268343236508978f;   // sin(2pi/16)
    const float C2 = 0.70710678118654752f;
    const float s  = (DIR > 0) ? 1.0f : -1.0f;
    v[5]  = cmul(v[5],  make_float2( C1, -s * S1));   // w16^1
    v[6]  = cmul(v[6],  make_float2( C2, -s * C2));   // w16^2
    v[7]  = cmul(v[7],  make_float2( S1, -s * C1));   // w16^3
    v[9]  = cmul(v[9],  make_float2( C2, -s * C2));   // w16^2
    v[10] = cmul(v[10], make_float2(0.f, -s      ));  // w16^4
    v[11] = cmul(v[11], make_float2(-C2, -s * C2));   // w16^6
    v[13] = cmul(v[13], make_float2( S1, -s * C1));   // w16^3
    v[14] = cmul(v[14], make_float2(-C2, -s * C2));   // w16^6
    v[15] = cmul(v[15], make_float2(-C1,  s * S1));   // w16^9
    #pragma unroll
    for (int k2 = 0; k2 < 4; k2++)
        dft4<DIR>(v[4 * k2], v[4 * k2 + 1], v[4 * k2 + 2], v[4 * k2 + 3]);
}

// One radix-16 Stockham DIT stage: v[r] = src[j + r*512] * w^(jq*r/(16*S)),
// y = DFT16(v), dst[jq + S*(16*jp + o)] = y[o].
template<int S, int DIR, bool PS, bool PD>
__device__ __forceinline__ void stage16(const float2* __restrict__ src,
                                        float2* __restrict__ dst,
                                        const float2* __restrict__ tw,
                                        const float2* __restrict__ tw16,
                                        int j) {
    float2 v[16];
    #pragma unroll
    for (int r = 0; r < 16; r++) {
        int a = j + r * (FFT_N / 16);
        v[r] = src[PS ? PADI(a) : a];
    }
    const int jq = j & (S - 1);
    {
        // w1 = exp(-2*pi*i*jq/(16*S)); chain w^r = w^(r-1)*w1.
        float2 w1 = (S == 16) ? tw16[jq] : tw[jq * (512 / S)];
        if (DIR < 0) w1.y = -w1.y;
        float2 w = w1;
        #pragma unroll
        for (int r = 1; r < 16; r++) {
            v[r] = cmul(v[r], w);
            if (r < 15) w = cmul(w, w1);
        }
    }
    dft16<DIR>(v);
    const int base = jq + (j / S) * (S * 16);
    #pragma unroll
    for (int o = 0; o < 16; o++) {
        int slot = ((o & 3) << 2) | (o >> 2);
        int a = base + S * o;
        dst[PD ? PADI(a) : a] = v[slot];
    }
}

__global__ __launch_bounds__(NT, 1)
void surrogate_kernel(const float* __restrict__ wave,
                      const float* __restrict__ phases,
                      const float* __restrict__ mask,
                      float* __restrict__ out) {
    const int blk = blockIdx.x;
    const int b   = blk >> 5;
    const int c0  = (blk & 31) * 2;
    const int tid = threadIdx.x;

    const bool s0 = mask[b * CH + c0]     < 0.5f;
    const bool s1 = mask[b * CH + c0 + 1] < 0.5f;

    const float* wbase = wave   + (size_t)b * FFT_N * CH + c0;
    const float* pbase = phases + (size_t)b * FFT_N * CH + c0;
    float*       obase = out    + (size_t)b * FFT_N * CH + c0;

    if (!s0 && !s1) {
        #pragma unroll 4
        for (int t = tid; t < FFT_N; t += NT)
            *(float2*)(obase + (size_t)t * CH) = *(const float2*)(wbase + (size_t)t * CH);
        return;
    }

    extern __shared__ float2 sm[];
    float2* bufA = sm;                       // 8192
    float2* bufB = sm + 8192;                // 8704 (padded layout)
    float2* tw   = sm + 8192 + 8704;         // 4096: tw[m] = e^{-2 pi i m/8192}
    float2* tw16 = tw + 4096;                // 16:   tw16[m] = e^{-2 pi i m/256}

    for (int m = tid; m < 4096; m += NT) {
        float sv, cv;
        sincospif(-(float)m / 4096.0f, &sv, &cv);
        tw[m] = make_float2(cv, sv);
    }
    if (tid < 16) {
        float sv, cv;
        sincospif(-(float)tid / 128.0f, &sv, &cv);
        tw16[tid] = make_float2(cv, sv);
    }

    // ---- Forward stage 1 (S=1, radix-16): gmem -> regs -> bufB(pad). -----
    // Channels that keep the original are written out during this load.
    {
        float2 v[16];
        #pragma unroll
        for (int r = 0; r < 16; r++) {
            int t = tid + r * (FFT_N / 16);
            float2 x = *(const float2*)(wbase + (size_t)t * CH);
            v[r] = x;
            if (!s0) obase[(size_t)t * CH]     = x.x;
            if (!s1) obase[(size_t)t * CH + 1] = x.y;
        }
        dft16<1>(v);
        const int base = tid * 16;
        #pragma unroll
        for (int o = 0; o < 16; o++) {
            int slot = ((o & 3) << 2) | (o >> 2);
            bufB[PADI(base + o)] = v[slot];
        }
    }
    __syncthreads();
    stage16<16,  1, true,  false>(bufB, bufA, tw, tw16, tid);
    __syncthreads();
    stage16<256, 1, false, true >(bufA, bufB, tw, tw16, tid);
    __syncthreads();
    // Forward stage 4 (radix-2, s=4096): bufB(pad) -> bufA. Natural order out.
    #pragma unroll
    for (int i = 0; i < 8; i++) {
        int j = tid + i * NT;
        float2 v0 = bufB[PADI(j)];
        float2 v1 = bufB[PADI(j + 4096)];
        v1 = cmul(v1, tw[j]);
        bufA[j]        = cadd(v0, v1);
        bufA[j + 4096] = csub(v0, v1);
    }
    __syncthreads();

    // ---- Spectrum rebuild (in-place in bufA) ------------------------------
    // Z = FFT(x1 + i*x2). Amplitudes via Hermitian unpack; new Hermitian
    // spectra H1,H2 from random phases; W = H1 + i*H2 so one IFFT yields both.
    {
        const float TWO_PI = 6.283185307179586476925f;
        const float scale = 0.25f / (float)FFT_N;
        for (int k = tid; k <= FFT_N / 2; k += NT) {
            const int nk = (FFT_N - k) & (FFT_N - 1);
            float2 z1 = bufA[k];
            float2 z2 = bufA[nk];
            float ax = z1.x + z2.x, ay = z1.y - z2.y;
            float bx = z1.y + z2.y, by = z2.x - z1.x;
            float amp1 = sqrtf(fmaf(ax, ax, ay * ay)) * scale;
            float amp2 = sqrtf(fmaf(bx, bx, by * by)) * scale;

            float2 pk  = *(const float2*)(pbase + (size_t)k  * CH);
            float2 pnk = *(const float2*)(pbase + (size_t)nk * CH);
            float s1k, c1k, s1n, c1n, s2k, c2k, s2n, c2n;
            __sincosf(TWO_PI * pk.x,  &s1k, &c1k);
            __sincosf(TWO_PI * pnk.x, &s1n, &c1n);
            __sincosf(TWO_PI * pk.y,  &s2k, &c2k);
            __sincosf(TWO_PI * pnk.y, &s2n, &c2n);

            float h1x = amp1 * (c1k + c1n), h1y = amp1 * (s1k - s1n);
            float h2x = amp2 * (c2k + c2n), h2y = amp2 * (s2k - s2n);

            bufA[k]  = make_float2(h1x - h2y, h1y + h2x);
            bufA[nk] = make_float2(h1x + h2y, h2x - h1y);
        }
    }
    __syncthreads();

    // ---- Inverse FFT -------------------------------------------------------
    // Stage 1 (S=1): bufA -> bufB(pad)
    {
        float2 v[16];
        #pragma unroll
        for (int r = 0; r < 16; r++)
            v[r] = bufA[tid + r * (FFT_N / 16)];
        dft16<-1>(v);
        const int base = tid * 16;
        #pragma unroll
        for (int o = 0; o < 16; o++) {
            int slot = ((o & 3) << 2) | (o >> 2);
            bufB[PADI(base + o)] = v[slot];
        }
    }
    __syncthreads();
    stage16<16,  -1, true,  false>(bufB, bufA, tw, tw16, tid);
    __syncthreads();
    stage16<256, -1, false, true >(bufA, bufB, tw, tw16, tid);
    __syncthreads();
    // Inverse stage 4 (radix-2): bufB(pad) -> gmem, masked.
    #pragma unroll
    for (int i = 0; i < 8; i++) {
        int j = tid + i * NT;
        float2 v0 = bufB[PADI(j)];
        float2 v1 = bufB[PADI(j + 4096)];
        float2 w = tw[j]; w.y = -w.y;
        v1 = cmul(v1, w);
        float2 y0 = cadd(v0, v1);
        float2 y1 = csub(v0, v1);
        if (s0 && s1) {
            *(float2*)(obase + (size_t)j * CH)          = y0;
            *(float2*)(obase + (size_t)(j + 4096) * CH) = y1;
        } else if (s0) {
            obase[(size_t)j * CH]          = y0.x;
            obase[(size_t)(j + 4096) * CH] = y1.x;
        } else {
            obase[(size_t)j * CH + 1]          = y0.y;
            obase[(size_t)(j + 4096) * CH + 1] = y1.y;
        }
    }
}

extern "C" void kernel_launch(void* const* d_in, const int* in_sizes, int n_in,
                              void* d_out, int out_size) {
    const float* wave   = (const float*)d_in[0];
    const float* phases = (const float*)d_in[1];
    const float* maskp  = (const float*)d_in[2];
    float* out = (float*)d_out;

    const int B = in_sizes[0] / (FFT_N * CH);
    const int smem = (8192 + 8704 + 4096 + 16) * (int)sizeof(float2);   // 168,064 B

    cudaFuncSetAttribute(surrogate_kernel,
                         cudaFuncAttributeMaxDynamicSharedMemorySize, smem);
    surrogate_kernel<<<B * (CH / 2), NT, smem>>>(wave, phases, maskp, out);
}

// round 4
// speedup vs baseline: 1.3998x; 1.0570x over previous
#include <cuda_runtime.h>
#include <cstddef>

#define FFT_N 8192
#define NT    1024
#define CH    64

// XOR swizzle on float2 index: conflict-free for all access patterns used
// here (verified per-pattern), bijective within any 256-element span.
#define SWZ(a) ((a) ^ (((a) >> 4) & 15))

__device__ __forceinline__ float2 cmul(float2 a, float2 b) {
    return make_float2(fmaf(a.x, b.x, -a.y * b.y), fmaf(a.x, b.y, a.y * b.x));
}
__device__ __forceinline__ float2 cadd(float2 a, float2 b) { return make_float2(a.x + b.x, a.y + b.y); }
__device__ __forceinline__ float2 csub(float2 a, float2 b) { return make_float2(a.x - b.x, a.y - b.y); }

// In-place DFT4. DIR=+1 forward, DIR=-1 inverse. Outputs in natural order.
template<int DIR>
__device__ __forceinline__ void dft4(float2& a, float2& b, float2& c, float2& d) {
    float2 t0 = cadd(a, c), t1 = csub(a, c);
    float2 t2 = cadd(b, d), t3 = csub(b, d);
    a = cadd(t0, t2);
    c = csub(t0, t2);
    if (DIR > 0) {
        b = make_float2(t1.x + t3.y, t1.y - t3.x);
        d = make_float2(t1.x - t3.y, t1.y + t3.x);
    } else {
        b = make_float2(t1.x - t3.y, t1.y + t3.x);
        d = make_float2(t1.x + t3.y, t1.y - t3.x);
    }
}

// In-place DFT8 (2x4 split), outputs X[0..7] in natural order in v[0..7].
template<int DIR>
__device__ __forceinline__ void dft8(float2 v[8]) {
    dft4<DIR>(v[0], v[2], v[4], v[6]);   // even samples -> Y0[k2] in v[2k2]
    dft4<DIR>(v[1], v[3], v[5], v[7]);   // odd  samples -> Y1[k2] in v[2k2+1]
    const float C2 = 0.70710678118654752f;
    const float s  = (DIR > 0) ? 1.0f : -1.0f;
    v[3] = cmul(v[3], make_float2( C2, -s * C2));   // w8^1
    v[5] = cmul(v[5], make_float2(0.f, -s      ));  // w8^2
    v[7] = cmul(v[7], make_float2(-C2, -s * C2));   // w8^3
    float2 y[8];
    #pragma unroll
    for (int k2 = 0; k2 < 4; k2++) {
        y[k2]     = cadd(v[2 * k2], v[2 * k2 + 1]);
        y[k2 + 4] = csub(v[2 * k2], v[2 * k2 + 1]);
    }
    #pragma unroll
    for (int o = 0; o < 8; o++) v[o] = y[o];
}

// One radix-8 Stockham DIT stage over shared memory.
// v[r] = src[j + r*1024] * w^(jq*r), w = exp(DIR * -2*pi*i * jq/(8S));
// dst[jq + 8S*jp + S*o] = DFT8(v)[o].
template<int S, int DIR>
__device__ __forceinline__ void stage8(const float2* __restrict__ src,
                                       float2* __restrict__ dst, int j) {
    float2 v[8];
    #pragma unroll
    for (int r = 0; r < 8; r++)
        v[r] = src[SWZ(j + r * (FFT_N / 8))];
    const int jq = j & (S - 1);
    if (S > 1) {
        float ss, cc;
        sincospif((DIR > 0 ? -2.0f : 2.0f) * (float)jq / (8.0f * (float)S), &ss, &cc);
        float2 w1 = make_float2(cc, ss);
        float2 w  = w1;
        #pragma unroll
        for (int r = 1; r < 8; r++) {
            v[r] = cmul(v[r], w);
            if (r < 7) w = cmul(w, w1);
        }
    }
    dft8<DIR>(v);
    const int base = jq + (j / S) * (S * 8);
    #pragma unroll
    for (int o = 0; o < 8; o++)
        dst[SWZ(base + S * o)] = v[o];
}

__global__ __launch_bounds__(NT, 1)
void surrogate_kernel(const float* __restrict__ wave,
                      const float* __restrict__ phases,
                      const float* __restrict__ mask,
                      float* __restrict__ out) {
    const int blk = blockIdx.x;
    const int b   = blk >> 5;
    const int c0  = (blk & 31) * 2;
    const int tid = threadIdx.x;

    const bool s0 = mask[b * CH + c0]     < 0.5f;
    const bool s1 = mask[b * CH + c0 + 1] < 0.5f;

    const float* wbase = wave   + (size_t)b * FFT_N * CH + c0;
    const float* pbase = phases + (size_t)b * FFT_N * CH + c0;
    float*       obase = out    + (size_t)b * FFT_N * CH + c0;

    if (!s0 && !s1) {
        #pragma unroll 4
        for (int t = tid; t < FFT_N; t += NT)
            *(float2*)(obase + (size_t)t * CH) = *(const float2*)(wbase + (size_t)t * CH);
        return;
    }

    extern __shared__ float2 sm[];
    float2* B0 = sm;            // 8192 float2
    float2* B1 = sm + FFT_N;    // 8192 float2

    // ---- Forward stage 1 (S=1): gmem -> regs -> B1 -------------------------
    {
        float2 v[8];
        #pragma unroll
        for (int r = 0; r < 8; r++) {
            int t = tid + r * (FFT_N / 8);
            float2 x = *(const float2*)(wbase + (size_t)t * CH);
            v[r] = x;
            if (!s0) obase[(size_t)t * CH]     = x.x;
            if (!s1) obase[(size_t)t * CH + 1] = x.y;
        }
        dft8<1>(v);
        #pragma unroll
        for (int o = 0; o < 8; o++)
            B1[SWZ(8 * tid + o)] = v[o];
    }
    __syncthreads();
    stage8<8,   1>(B1, B0, tid);  __syncthreads();
    stage8<64,  1>(B0, B1, tid);  __syncthreads();
    stage8<512, 1>(B1, B0, tid);  __syncthreads();
    // Forward radix-2 (s=4096): B0 -> B1, natural-order spectrum out.
    #pragma unroll
    for (int i = 0; i < FFT_N / 2 / NT; i++) {
        int j = tid + i * NT;
        float2 v0 = B0[SWZ(j)];
        float2 v1 = B0[SWZ(j + 4096)];
        float ss, cc;
        sincospif(-(float)j / 4096.0f, &ss, &cc);
        v1 = cmul(v1, make_float2(cc, ss));
        B1[SWZ(j)]        = cadd(v0, v1);
        B1[SWZ(j + 4096)] = csub(v0, v1);
    }
    __syncthreads();

    // ---- Spectrum rebuild (in place in B1) ---------------------------------
    // Z = FFT(x1 + i*x2): Hermitian-unpack amplitudes, apply random phases,
    // re-symmetrize into W = H1 + i*H2 so one IFFT yields both real outputs.
    {
        const float TWO_PI = 6.283185307179586476925f;
        const float scale  = 0.25f / (float)FFT_N;
        for (int k = tid; k <= FFT_N / 2; k += NT) {
            const int nk = (FFT_N - k) & (FFT_N - 1);
            float2 z1 = B1[SWZ(k)];
            float2 z2 = B1[SWZ(nk)];
            float ax = z1.x + z2.x, ay = z1.y - z2.y;
            float bx = z1.y + z2.y, by = z2.x - z1.x;
            float amp1 = sqrtf(fmaf(ax, ax, ay * ay)) * scale;
            float amp2 = sqrtf(fmaf(bx, bx, by * by)) * scale;

            float2 pk  = *(const float2*)(pbase + (size_t)k  * CH);
            float2 pnk = *(const float2*)(pbase + (size_t)nk * CH);
            float s1k, c1k, s1n, c1n, s2k, c2k, s2n, c2n;
            __sincosf(TWO_PI * pk.x,  &s1k, &c1k);
            __sincosf(TWO_PI * pnk.x, &s1n, &c1n);
            __sincosf(TWO_PI * pk.y,  &s2k, &c2k);
            __sincosf(TWO_PI * pnk.y, &s2n, &c2n);

            float h1x = amp1 * (c1k + c1n), h1y = amp1 * (s1k - s1n);
            float h2x = amp2 * (c2k + c2n), h2y = amp2 * (s2k - s2n);

            B1[SWZ(k)]  = make_float2(h1x - h2y, h1y + h2x);
            B1[SWZ(nk)] = make_float2(h1x + h2y, h2x - h1y);
        }
    }
    __syncthreads();

    // ---- Inverse FFT --------------------------------------------------------
    stage8<1,   -1>(B1, B0, tid); __syncthreads();
    stage8<8,   -1>(B0, B1, tid); __syncthreads();
    stage8<64,  -1>(B1, B0, tid); __syncthreads();
    stage8<512, -1>(B0, B1, tid); __syncthreads();
    // Inverse radix-2: B1 -> gmem, masked. Re = ch c0, Im = ch c0+1.
    #pragma unroll
    for (int i = 0; i < FFT_N / 2 / NT; i++) {
        int j = tid + i * NT;
        float2 v0 = B1[SWZ(j)];
        float2 v1 = B1[SWZ(j + 4096)];
        float ss, cc;
        sincospif((float)j / 4096.0f, &ss, &cc);
        v1 = cmul(v1, make_float2(cc, ss));
        float2 y0 = cadd(v0, v1);
        float2 y1 = csub(v0, v1);
        if (s0 && s1) {
            *(float2*)(obase + (size_t)j * CH)          = y0;
            *(float2*)(obase + (size_t)(j + 4096) * CH) = y1;
        } else if (s0) {
            obase[(size_t)j * CH]          = y0.x;
            obase[(size_t)(j + 4096) * CH] = y1.x;
        } else {
            obase[(size_t)j * CH + 1]          = y0.y;
            obase[(size_t)(j + 4096) * CH + 1] = y1.y;
        }
    }
}

extern "C" void kernel_launch(void* const* d_in, const int* in_sizes, int n_in,
                              void* d_out, int out_size) {
    const float* wave   = (const float*)d_in[0];
    const float* phases = (const float*)d_in[1];
    const float* maskp  = (const float*)d_in[2];
    float* out = (float*)d_out;

    const int B = in_sizes[0] / (FFT_N * CH);
    const int smem = 2 * FFT_N * (int)sizeof(float2);   // 131,072 B

    cudaFuncSetAttribute(surrogate_kernel,
                         cudaFuncAttributeMaxDynamicSharedMemorySize, smem);
    surrogate_kernel<<<B * (CH / 2), NT, smem>>>(wave, phases, maskp, out);
}

// round 5
// speedup vs baseline: 1.9121x; 1.3660x over previous
#include <cuda_runtime.h>
#include <cstddef>

#define FFT_N 8192
#define NT    1024
#define CH    64

// XOR swizzle on float2 index: conflict-free (<=2-way worst case) for all
// access patterns used here.
#define SWZ(a) ((a) ^ (((a) >> 4) & 15))

__device__ __forceinline__ float2 cmul(float2 a, float2 b) {
    return make_float2(fmaf(a.x, b.x, -a.y * b.y), fmaf(a.x, b.y, a.y * b.x));
}
__device__ __forceinline__ float2 cadd(float2 a, float2 b) { return make_float2(a.x + b.x, a.y + b.y); }
__device__ __forceinline__ float2 csub(float2 a, float2 b) { return make_float2(a.x - b.x, a.y - b.y); }

template<int DIR>
__device__ __forceinline__ void dft4(float2& a, float2& b, float2& c, float2& d) {
    float2 t0 = cadd(a, c), t1 = csub(a, c);
    float2 t2 = cadd(b, d), t3 = csub(b, d);
    a = cadd(t0, t2);
    c = csub(t0, t2);
    if (DIR > 0) {
        b = make_float2(t1.x + t3.y, t1.y - t3.x);
        d = make_float2(t1.x - t3.y, t1.y + t3.x);
    } else {
        b = make_float2(t1.x - t3.y, t1.y + t3.x);
        d = make_float2(t1.x + t3.y, t1.y - t3.x);
    }
}

// In-place DFT8, natural-order outputs.
template<int DIR>
__device__ __forceinline__ void dft8(float2 v[8]) {
    dft4<DIR>(v[0], v[2], v[4], v[6]);
    dft4<DIR>(v[1], v[3], v[5], v[7]);
    const float C2 = 0.70710678118654752f;
    const float s  = (DIR > 0) ? 1.0f : -1.0f;
    v[3] = cmul(v[3], make_float2( C2, -s * C2));
    v[5] = cmul(v[5], make_float2(0.f, -s      ));
    v[7] = cmul(v[7], make_float2(-C2, -s * C2));
    float2 y[8];
    #pragma unroll
    for (int k2 = 0; k2 < 4; k2++) {
        y[k2]     = cadd(v[2 * k2], v[2 * k2 + 1]);
        y[k2 + 4] = csub(v[2 * k2], v[2 * k2 + 1]);
    }
    #pragma unroll
    for (int o = 0; o < 8; o++) v[o] = y[o];
}

// Read+twiddle+dft8 of one radix-8 Stockham stage for one buffer (into regs).
template<int S, int DIR>
__device__ __forceinline__ void stage_read(const float2* __restrict__ buf, int j,
                                           float2 w1, float2 v[8]) {
    #pragma unroll
    for (int r = 0; r < 8; r++)
        v[r] = buf[SWZ(j + r * (FFT_N / 8))];
    if (S > 1) {
        float2 w = w1;
        #pragma unroll
        for (int r = 1; r < 8; r++) {
            v[r] = cmul(v[r], w);
            if (r < 7) w = cmul(w, w1);
        }
    }
    dft8<DIR>(v);
}

template<int S>
__device__ __forceinline__ void stage_write(float2* __restrict__ buf, int j,
                                            const float2 v[8]) {
    const int jq   = j & (S - 1);
    const int base = jq + (j / S) * (S * 8);
    #pragma unroll
    for (int o = 0; o < 8; o++)
        buf[SWZ(base + S * o)] = v[o];
}

// One in-place radix-8 stage applied to both buffers (guarded per pair).
// Contract: entered and exited with buffers consistent across the CTA.
template<int S, int DIR>
__device__ __forceinline__ void stage_pair(float2* b0, float2* b1, int j,
                                           bool p0, bool p1) {
    float2 w1 = make_float2(1.f, 0.f);
    if (S > 1) {
        float ss, cc;
        sincospif((DIR > 0 ? -2.0f : 2.0f) * (float)(j & (S - 1)) / (8.0f * (float)S), &ss, &cc);
        w1 = make_float2(cc, ss);
    }
    float2 v[8];
    if (p0) stage_read<S, DIR>(b0, j, w1, v);
    __syncthreads();
    if (p0) stage_write<S>(b0, j, v);
    if (p1) stage_read<S, DIR>(b1, j, w1, v);
    __syncthreads();
    if (p1) stage_write<S>(b1, j, v);
    __syncthreads();
}

__global__ __launch_bounds__(NT, 1)
void surrogate_kernel(const float* __restrict__ wave,
                      const float* __restrict__ phases,
                      const float* __restrict__ mask,
                      float* __restrict__ out) {
    const int blk = blockIdx.x;
    const int b   = blk >> 4;          // 16 channel-quads per batch
    const int c0  = (blk & 15) * 4;
    const int tid = threadIdx.x;

    const bool s0 = mask[b * CH + c0]     < 0.5f;
    const bool s1 = mask[b * CH + c0 + 1] < 0.5f;
    const bool s2 = mask[b * CH + c0 + 2] < 0.5f;
    const bool s3 = mask[b * CH + c0 + 3] < 0.5f;
    const bool p0 = s0 | s1;           // pair 0 needs FFT
    const bool p1 = s2 | s3;           // pair 1 needs FFT

    const float4* w4 = (const float4*)(wave   + (size_t)b * FFT_N * CH + c0);
    const float4* p4 = (const float4*)(phases + (size_t)b * FFT_N * CH + c0);
    float4*       o4 = (float4*)      (out    + (size_t)b * FFT_N * CH + c0);

    if (!p0 && !p1) {
        #pragma unroll 4
        for (int t = tid; t < FFT_N; t += NT)
            o4[(size_t)t * 16] = w4[(size_t)t * 16];
        return;
    }

    extern __shared__ float2 sm[];
    float2* b0 = sm;            // pair 0: ch c0 + i*ch(c0+1)
    float2* b1 = sm + FFT_N;    // pair 1: ch c0+2 + i*ch(c0+3)

    // ---- Load: one float4 per time sample -> both buffers -----------------
    #pragma unroll
    for (int i = 0; i < FFT_N / NT; i++) {
        int t = tid + i * NT;
        float4 g = w4[(size_t)t * 16];
        b0[SWZ(t)] = make_float2(g.x, g.y);
        b1[SWZ(t)] = make_float2(g.z, g.w);
    }
    __syncthreads();

    // ---- Forward FFT: radix-8 x4 (in place) + radix-2 ----------------------
    stage_pair<1,   1>(b0, b1, tid, p0, p1);
    stage_pair<8,   1>(b0, b1, tid, p0, p1);
    stage_pair<64,  1>(b0, b1, tid, p0, p1);
    stage_pair<512, 1>(b0, b1, tid, p0, p1);
    #pragma unroll
    for (int i = 0; i < FFT_N / 2 / NT; i++) {
        int j = tid + i * NT;
        float ss, cc;
        sincospif(-(float)j / 4096.0f, &ss, &cc);
        float2 w = make_float2(cc, ss);
        if (p0) {
            float2 u0 = b0[SWZ(j)], u1 = cmul(b0[SWZ(j + 4096)], w);
            b0[SWZ(j)] = cadd(u0, u1);  b0[SWZ(j + 4096)] = csub(u0, u1);
        }
        if (p1) {
            float2 u0 = b1[SWZ(j)], u1 = cmul(b1[SWZ(j + 4096)], w);
            b1[SWZ(j)] = cadd(u0, u1);  b1[SWZ(j + 4096)] = csub(u0, u1);
        }
    }
    __syncthreads();

    // ---- Spectrum rebuild (in place; thread owns indices k and nk) --------
    // Z = FFT(xA + i*xB): Hermitian-unpack amplitudes, apply random phases,
    // re-symmetrize into W = H_A + i*H_B so one IFFT yields both real series.
    {
        const float TWO_PI = 6.283185307179586476925f;
        const float scale  = 0.25f / (float)FFT_N;
        for (int k = tid; k <= FFT_N / 2; k += NT) {
            const int nk = (FFT_N - k) & (FFT_N - 1);
            float4 pk  = p4[(size_t)k  * 16];
            float4 pnk = p4[(size_t)nk * 16];
            if (p0) {
                float2 z1 = b0[SWZ(k)], z2 = b0[SWZ(nk)];
                float ax = z1.x + z2.x, ay = z1.y - z2.y;
                float bx = z1.y + z2.y, by = z2.x - z1.x;
                float ampA = sqrtf(fmaf(ax, ax, ay * ay)) * scale;
                float ampB = sqrtf(fmaf(bx, bx, by * by)) * scale;
                float sk, ck, sn, cn, tk, dk, tn, dn;
                __sincosf(TWO_PI * pk.x,  &sk, &ck);
                __sincosf(TWO_PI * pnk.x, &sn, &cn);
                __sincosf(TWO_PI * pk.y,  &tk, &dk);
                __sincosf(TWO_PI * pnk.y, &tn, &dn);
                float h1x = ampA * (ck + cn), h1y = ampA * (sk - sn);
                float h2x = ampB * (dk + dn), h2y = ampB * (tk - tn);
                b0[SWZ(k)]  = make_float2(h1x - h2y, h1y + h2x);
                b0[SWZ(nk)] = make_float2(h1x + h2y, h2x - h1y);
            }
            if (p1) {
                float2 z1 = b1[SWZ(k)], z2 = b1[SWZ(nk)];
                float ax = z1.x + z2.x, ay = z1.y - z2.y;
                float bx = z1.y + z2.y, by = z2.x - z1.x;
                float ampA = sqrtf(fmaf(ax, ax, ay * ay)) * scale;
                float ampB = sqrtf(fmaf(bx, bx, by * by)) * scale;
                float sk, ck, sn, cn, tk, dk, tn, dn;
                __sincosf(TWO_PI * pk.z,  &sk, &ck);
                __sincosf(TWO_PI * pnk.z, &sn, &cn);
                __sincosf(TWO_PI * pk.w,  &tk, &dk);
                __sincosf(TWO_PI * pnk.w, &tn, &dn);
                float h1x = ampA * (ck + cn), h1y = ampA * (sk - sn);
                float h2x = ampB * (dk + dn), h2y = ampB * (tk - tn);
                b1[SWZ(k)]  = make_float2(h1x - h2y, h1y + h2x);
                b1[SWZ(nk)] = make_float2(h1x + h2y, h2x - h1y);
            }
        }
    }
    __syncthreads();

    // ---- Inverse FFT --------------------------------------------------------
    stage_pair<1,   -1>(b0, b1, tid, p0, p1);
    stage_pair<8,   -1>(b0, b1, tid, p0, p1);
    stage_pair<64,  -1>(b0, b1, tid, p0, p1);
    stage_pair<512, -1>(b0, b1, tid, p0, p1);

    // ---- Final radix-2 + reload + per-channel select + float4 store --------
    const bool all4 = s0 & s1 & s2 & s3;
    #pragma unroll
    for (int i = 0; i < FFT_N / 2 / NT; i++) {
        int j = tid + i * NT;
        float ss, cc;
        sincospif((float)j / 4096.0f, &ss, &cc);
        float2 w = make_float2(cc, ss);
        float2 y0 = make_float2(0.f, 0.f), y1 = y0, z0 = y0, z1 = y0;
        if (p0) {
            float2 u0 = b0[SWZ(j)], u1 = cmul(b0[SWZ(j + 4096)], w);
            y0 = cadd(u0, u1);  y1 = csub(u0, u1);
        }
        if (p1) {
            float2 u0 = b1[SWZ(j)], u1 = cmul(b1[SWZ(j + 4096)], w);
            z0 = cadd(u0, u1);  z1 = csub(u0, u1);
        }
        if (all4) {
            o4[(size_t)j * 16]          = make_float4(y0.x, y0.y, z0.x, z0.y);
            o4[(size_t)(j + 4096) * 16] = make_float4(y1.x, y1.y, z1.x, z1.y);
        } else {
            float4 ga = w4[(size_t)j * 16];
            float4 gb = w4[(size_t)(j + 4096) * 16];
            o4[(size_t)j * 16] = make_float4(s0 ? y0.x : ga.x, s1 ? y0.y : ga.y,
                                             s2 ? z0.x : ga.z, s3 ? z0.y : ga.w);
            o4[(size_t)(j + 4096) * 16] = make_float4(s0 ? y1.x : gb.x, s1 ? y1.y : gb.y,
                                                      s2 ? z1.x : gb.z, s3 ? z1.y : gb.w);
        }
    }
}

extern "C" void kernel_launch(void* const* d_in, const int* in_sizes, int n_in,
                              void* d_out, int out_size) {
    const float* wave   = (const float*)d_in[0];
    const float* phases = (const float*)d_in[1];
    const float* maskp  = (const float*)d_in[2];
    float* out = (float*)d_out;

    const int B = in_sizes[0] / (FFT_N * CH);
    const int smem = 2 * FFT_N * (int)sizeof(float2);   // 131,072 B

    cudaFuncSetAttribute(surrogate_kernel,
                         cudaFuncAttributeMaxDynamicSharedMemorySize, smem);
    surrogate_kernel<<<B * (CH / 4), NT, smem>>>(wave, phases, maskp, out);
}